// round 1
// baseline (speedup 1.0000x reference)
#include <cuda_runtime.h>

// GausSplatingHead: per-point 3D Gaussian covariance from (scale, quaternion).
//   q -> R (3x3 rotation), L = R * diag-broadcast(scale) (columnwise),
//   cov = L L^T, output upper-triangular 6 entries.
//
// Pure streaming kernel: 28 B in + 24 B out per point. Strategy: 4 points per
// thread so every global access is an aligned float4 (scales: 3x, rots: 4x,
// out: 6x float4).

__global__ __launch_bounds__(256) void gs_cov_vec4_kernel(
    const float4* __restrict__ scales4,  // 3 float4 per 4 points
    const float4* __restrict__ rots4,    // 4 float4 per 4 points
    float4* __restrict__ out4,           // 6 float4 per 4 points
    int nquads)
{
    int t = blockIdx.x * blockDim.x + threadIdx.x;
    if (t >= nquads) return;

    // Load 4 points' scales (12 floats) and rots (16 floats), all 128-bit.
    float4 sA = scales4[3 * t + 0];
    float4 sB = scales4[3 * t + 1];
    float4 sC = scales4[3 * t + 2];
    float s[12] = {sA.x, sA.y, sA.z, sA.w,
                   sB.x, sB.y, sB.z, sB.w,
                   sC.x, sC.y, sC.z, sC.w};

    float4 q0 = rots4[4 * t + 0];
    float4 q1 = rots4[4 * t + 1];
    float4 q2 = rots4[4 * t + 2];
    float4 q3 = rots4[4 * t + 3];
    float4 q[4] = {q0, q1, q2, q3};

    float o[24];

#pragma unroll
    for (int p = 0; p < 4; p++) {
        float r = q[p].x, x = q[p].y, y = q[p].z, z = q[p].w;
        float n2 = r * r + x * x + y * y + z * z;
        // R(q/||q||) has entries quadratic in q: use ss = 2/||q||^2 in place
        // of the usual factor 2 on a normalized quaternion. Exact same math.
        float ss = __fdividef(2.0f, n2);

        float xx = x * x * ss, yy = y * y * ss, zz = z * z * ss;
        float xy = x * y * ss, xz = x * z * ss, yz = y * z * ss;
        float rx = r * x * ss, ry = r * y * ss, rz = r * z * ss;

        float R00 = 1.0f - yy - zz, R01 = xy - rz, R02 = xz + ry;
        float R10 = xy + rz, R11 = 1.0f - xx - zz, R12 = yz - rx;
        float R20 = xz - ry, R21 = yz + rx, R22 = 1.0f - xx - yy;

        float s0 = s[3 * p + 0], s1 = s[3 * p + 1], s2 = s[3 * p + 2];
        float a = s0 * s0, b = s1 * s1, c = s2 * s2;

        // cov[i][k] = sum_j R[i][j] R[k][j] * s_j^2  (L = R * scale broadcast)
        o[6 * p + 0] = R00 * R00 * a + R01 * R01 * b + R02 * R02 * c;  // 00
        o[6 * p + 1] = R00 * R10 * a + R01 * R11 * b + R02 * R12 * c;  // 01
        o[6 * p + 2] = R00 * R20 * a + R01 * R21 * b + R02 * R22 * c;  // 02
        o[6 * p + 3] = R10 * R10 * a + R11 * R11 * b + R12 * R12 * c;  // 11
        o[6 * p + 4] = R10 * R20 * a + R11 * R21 * b + R12 * R22 * c;  // 12
        o[6 * p + 5] = R20 * R20 * a + R21 * R21 * b + R22 * R22 * c;  // 22
    }

#pragma unroll
    for (int i = 0; i < 6; i++) {
        out4[6 * t + i] = make_float4(o[4 * i + 0], o[4 * i + 1],
                                      o[4 * i + 2], o[4 * i + 3]);
    }
}

// Scalar tail for N not divisible by 4 (not expected here, but safe).
__global__ void gs_cov_tail_kernel(
    const float* __restrict__ scales,
    const float* __restrict__ rots,
    float* __restrict__ out,
    int start, int n)
{
    int i = start + blockIdx.x * blockDim.x + threadIdx.x;
    if (i >= n) return;

    float r = rots[4 * i + 0], x = rots[4 * i + 1];
    float y = rots[4 * i + 2], z = rots[4 * i + 3];
    float n2 = r * r + x * x + y * y + z * z;
    float ss = __fdividef(2.0f, n2);

    float xx = x * x * ss, yy = y * y * ss, zz = z * z * ss;
    float xy = x * y * ss, xz = x * z * ss, yz = y * z * ss;
    float rx = r * x * ss, ry = r * y * ss, rz = r * z * ss;

    float R00 = 1.0f - yy - zz, R01 = xy - rz, R02 = xz + ry;
    float R10 = xy + rz, R11 = 1.0f - xx - zz, R12 = yz - rx;
    float R20 = xz - ry, R21 = yz + rx, R22 = 1.0f - xx - yy;

    float s0 = scales[3 * i + 0], s1 = scales[3 * i + 1], s2 = scales[3 * i + 2];
    float a = s0 * s0, b = s1 * s1, c = s2 * s2;

    out[6 * i + 0] = R00 * R00 * a + R01 * R01 * b + R02 * R02 * c;
    out[6 * i + 1] = R00 * R10 * a + R01 * R11 * b + R02 * R12 * c;
    out[6 * i + 2] = R00 * R20 * a + R01 * R21 * b + R02 * R22 * c;
    out[6 * i + 3] = R10 * R10 * a + R11 * R11 * b + R12 * R12 * c;
    out[6 * i + 4] = R10 * R20 * a + R11 * R21 * b + R12 * R22 * c;
    out[6 * i + 5] = R20 * R20 * a + R21 * R21 * b + R22 * R22 * c;
}

extern "C" void kernel_launch(void* const* d_in, const int* in_sizes, int n_in,
                              void* d_out, int out_size)
{
    const float* scales = (const float*)d_in[0];  // [N,3]
    const float* rots   = (const float*)d_in[1];  // [N,4]
    float* out          = (float*)d_out;          // [N,6]

    int n = in_sizes[0] / 3;
    int nquads = n / 4;
    int rem_start = nquads * 4;

    if (nquads > 0) {
        int threads = 256;
        int blocks = (nquads + threads - 1) / threads;
        gs_cov_vec4_kernel<<<blocks, threads>>>(
            (const float4*)scales, (const float4*)rots, (float4*)out, nquads);
    }
    if (rem_start < n) {
        int rem = n - rem_start;
        gs_cov_tail_kernel<<<(rem + 127) / 128, 128>>>(
            scales, rots, out, rem_start, n);
    }
}

// round 2
// speedup vs baseline: 1.2700x; 1.2700x over previous
#include <cuda_runtime.h>

// GausSplatingHead: per-point 3D Gaussian covariance from (scale, quaternion).
// Streaming kernel (28 B in + 24 B out per point). R2 strategy: smem staging
// so ALL global traffic is dense lane-contiguous float4 (4 sectors / 4 lines
// per LDG/STG.128 instead of 12-24 with the strided R1 layout).
//
// Block = 256 threads = 256 points:
//   phase 1: coalesced float4 loads GMEM -> smem (scales 192 f4, rots 256 f4)
//   phase 2: each thread computes one point from smem
//   phase 3: coalesced float4 stores smem -> GMEM (384 f4)

#define TPB 256

__global__ __launch_bounds__(TPB) void gs_cov_tiled_kernel(
    const float4* __restrict__ scales4,  // [n*3/4] float4
    const float4* __restrict__ rots4,    // [n] float4
    float4* __restrict__ out4,           // [n*6/4] float4
    int n)
{
    __shared__ float  s_scales[TPB * 3];      // 3 KB
    __shared__ float4 s_rots[TPB];            // 4 KB
    __shared__ float  s_out[TPB * 6];         // 6 KB

    const int tid  = threadIdx.x;
    const int base = blockIdx.x * TPB;        // first point of this tile

    if (base + TPB <= n) {
        // ---- fast path: full tile, everything dense float4 ----

        // scales: 256 pts * 3 floats = 768 floats = 192 float4
        if (tid < 192)
            ((float4*)s_scales)[tid] = scales4[(size_t)base * 3 / 4 + tid];
        // rots: 256 float4
        s_rots[tid] = rots4[base + tid];
        __syncthreads();

        // compute one point
        {
            float4 q = s_rots[tid];                 // LDS.128, dense: no conflict
            float r = q.x, x = q.y, y = q.z, z = q.w;
            float n2 = r * r + x * x + y * y + z * z;
            // R(q/||q||) entries are quadratic in q: fold normalization into
            // the factor 2 -> ss = 2/||q||^2. Algebraically identical.
            float ss = __fdividef(2.0f, n2);

            float xx = x * x * ss, yy = y * y * ss, zz = z * z * ss;
            float xy = x * y * ss, xz = x * z * ss, yz = y * z * ss;
            float rx = r * x * ss, ry = r * y * ss, rz = r * z * ss;

            float R00 = 1.0f - yy - zz, R01 = xy - rz, R02 = xz + ry;
            float R10 = xy + rz, R11 = 1.0f - xx - zz, R12 = yz - rx;
            float R20 = xz - ry, R21 = yz + rx, R22 = 1.0f - xx - yy;

            float s0 = s_scales[3 * tid + 0];       // stride-3: conflict-free
            float s1 = s_scales[3 * tid + 1];
            float s2 = s_scales[3 * tid + 2];
            float a = s0 * s0, b = s1 * s1, c = s2 * s2;

            // cov = R diag(s^2) R^T, upper triangle
            s_out[6 * tid + 0] = R00 * R00 * a + R01 * R01 * b + R02 * R02 * c;
            s_out[6 * tid + 1] = R00 * R10 * a + R01 * R11 * b + R02 * R12 * c;
            s_out[6 * tid + 2] = R00 * R20 * a + R01 * R21 * b + R02 * R22 * c;
            s_out[6 * tid + 3] = R10 * R10 * a + R11 * R11 * b + R12 * R12 * c;
            s_out[6 * tid + 4] = R10 * R20 * a + R11 * R21 * b + R12 * R22 * c;
            s_out[6 * tid + 5] = R20 * R20 * a + R21 * R21 * b + R22 * R22 * c;
        }
        __syncthreads();

        // out: 256 pts * 6 floats = 1536 floats = 384 float4
        size_t obase = (size_t)base * 6 / 4;
        out4[obase + tid]       = ((const float4*)s_out)[tid];
        if (tid < 128)
            out4[obase + 256 + tid] = ((const float4*)s_out)[256 + tid];
    } else {
        // ---- tail tile (rare): scalar global path ----
        int i = base + tid;
        if (i < n) {
            const float* scales = (const float*)scales4;
            const float* rots   = (const float*)rots4;
            float* out          = (float*)out4;

            float r = rots[4 * i + 0], x = rots[4 * i + 1];
            float y = rots[4 * i + 2], z = rots[4 * i + 3];
            float n2 = r * r + x * x + y * y + z * z;
            float ss = __fdividef(2.0f, n2);

            float xx = x * x * ss, yy = y * y * ss, zz = z * z * ss;
            float xy = x * y * ss, xz = x * z * ss, yz = y * z * ss;
            float rx = r * x * ss, ry = r * y * ss, rz = r * z * ss;

            float R00 = 1.0f - yy - zz, R01 = xy - rz, R02 = xz + ry;
            float R10 = xy + rz, R11 = 1.0f - xx - zz, R12 = yz - rx;
            float R20 = xz - ry, R21 = yz + rx, R22 = 1.0f - xx - yy;

            float s0 = scales[3 * i + 0], s1 = scales[3 * i + 1], s2 = scales[3 * i + 2];
            float a = s0 * s0, b = s1 * s1, c = s2 * s2;

            out[6 * i + 0] = R00 * R00 * a + R01 * R01 * b + R02 * R02 * c;
            out[6 * i + 1] = R00 * R10 * a + R01 * R11 * b + R02 * R12 * c;
            out[6 * i + 2] = R00 * R20 * a + R01 * R21 * b + R02 * R22 * c;
            out[6 * i + 3] = R10 * R10 * a + R11 * R11 * b + R12 * R12 * c;
            out[6 * i + 4] = R10 * R20 * a + R11 * R21 * b + R12 * R22 * c;
            out[6 * i + 5] = R20 * R20 * a + R21 * R21 * b + R22 * R22 * c;
        }
    }
}

extern "C" void kernel_launch(void* const* d_in, const int* in_sizes, int n_in,
                              void* d_out, int out_size)
{
    const float4* scales = (const float4*)d_in[0];  // [N,3]
    const float4* rots   = (const float4*)d_in[1];  // [N,4]
    float4* out          = (float4*)d_out;          // [N,6]

    int n = in_sizes[0] / 3;
    int blocks = (n + TPB - 1) / TPB;
    gs_cov_tiled_kernel<<<blocks, TPB>>>(scales, rots, out, n);
}

// round 3
// speedup vs baseline: 1.3295x; 1.0469x over previous
#include <cuda_runtime.h>

// GausSplatingHead: per-point 3D Gaussian covariance from (scale, quaternion).
// R3: 512-point tiles, 2 points/thread.
//   - rots: direct dense float4 loads (no smem round trip)
//   - scales: smem-staged (stride-3 floats is conflict-free on read)
//   - out: smem-staged, 3 dense float4 stores per thread
// Goal: deeper MLP per barrier, fewer barriers/point, less L1 traffic.

#define TPB  256
#define TILE 512   // points per block

__device__ __forceinline__ void cov_from_q(
    float r, float x, float y, float z,
    float s0, float s1, float s2, float* o /*6*/)
{
    float n2 = r * r + x * x + y * y + z * z;
    // R(q/||q||) entries are quadratic in q: fold the normalization into the
    // factor 2 -> ss = 2/||q||^2. Algebraically identical to the reference.
    float ss = __fdividef(2.0f, n2);

    float xx = x * x * ss, yy = y * y * ss, zz = z * z * ss;
    float xy = x * y * ss, xz = x * z * ss, yz = y * z * ss;
    float rx = r * x * ss, ry = r * y * ss, rz = r * z * ss;

    float R00 = 1.0f - yy - zz, R01 = xy - rz, R02 = xz + ry;
    float R10 = xy + rz, R11 = 1.0f - xx - zz, R12 = yz - rx;
    float R20 = xz - ry, R21 = yz + rx, R22 = 1.0f - xx - yy;

    float a = s0 * s0, b = s1 * s1, c = s2 * s2;

    o[0] = R00 * R00 * a + R01 * R01 * b + R02 * R02 * c;  // 00
    o[1] = R00 * R10 * a + R01 * R11 * b + R02 * R12 * c;  // 01
    o[2] = R00 * R20 * a + R01 * R21 * b + R02 * R22 * c;  // 02
    o[3] = R10 * R10 * a + R11 * R11 * b + R12 * R12 * c;  // 11
    o[4] = R10 * R20 * a + R11 * R21 * b + R12 * R22 * c;  // 12
    o[5] = R20 * R20 * a + R21 * R21 * b + R22 * R22 * c;  // 22
}

__global__ __launch_bounds__(TPB) void gs_cov_t512_kernel(
    const float4* __restrict__ scales4,  // [n*3/4]
    const float4* __restrict__ rots4,    // [n]
    float4* __restrict__ out4,           // [n*6/4]
    int n)
{
    __shared__ float s_scales[TILE * 3];   // 6 KB (384 float4)
    __shared__ float s_out[TILE * 6];      // 12 KB (768 float4)

    const int tid  = threadIdx.x;
    const int base = blockIdx.x * TILE;

    if (base + TILE <= n) {
        // ---- fast path ----
        // Issue all global loads up front (max MLP before the barrier).
        size_t sbase = (size_t)base * 3 / 4;            // float4 index
        float4 q0 = rots4[base + tid];                   // point p0 = tid
        float4 q1 = rots4[base + TPB + tid];             // point p1 = tid+256
        float4 sc0 = scales4[sbase + tid];               // 384 f4 total:
        float4 sc1 = (tid < 128) ? scales4[sbase + TPB + tid]
                                 : make_float4(0, 0, 0, 0);

        ((float4*)s_scales)[tid] = sc0;
        if (tid < 128) ((float4*)s_scales)[TPB + tid] = sc1;
        __syncthreads();

        float o0[6], o1[6];
        {
            int p = tid;
            cov_from_q(q0.x, q0.y, q0.z, q0.w,
                       s_scales[3 * p + 0], s_scales[3 * p + 1], s_scales[3 * p + 2], o0);
        }
        {
            int p = TPB + tid;
            cov_from_q(q1.x, q1.y, q1.z, q1.w,
                       s_scales[3 * p + 0], s_scales[3 * p + 1], s_scales[3 * p + 2], o1);
        }

#pragma unroll
        for (int k = 0; k < 6; k++) s_out[6 * tid + k] = o0[k];
#pragma unroll
        for (int k = 0; k < 6; k++) s_out[6 * (TPB + tid) + k] = o1[k];
        __syncthreads();

        // 768 dense float4 stores (3 per thread)
        size_t obase = (size_t)base * 6 / 4;
        const float4* so4 = (const float4*)s_out;
        out4[obase + tid]            = so4[tid];
        out4[obase + TPB + tid]      = so4[TPB + tid];
        out4[obase + 2 * TPB + tid]  = so4[2 * TPB + tid];
    } else {
        // ---- tail tile (rare): scalar global path ----
        const float* scales = (const float*)scales4;
        const float* rots   = (const float*)rots4;
        float* out          = (float*)out4;
#pragma unroll
        for (int p = 0; p < 2; p++) {
            int i = base + p * TPB + tid;
            if (i < n) {
                float o[6];
                cov_from_q(rots[4 * i + 0], rots[4 * i + 1],
                           rots[4 * i + 2], rots[4 * i + 3],
                           scales[3 * i + 0], scales[3 * i + 1], scales[3 * i + 2], o);
#pragma unroll
                for (int k = 0; k < 6; k++) out[6 * i + k] = o[k];
            }
        }
    }
}

extern "C" void kernel_launch(void* const* d_in, const int* in_sizes, int n_in,
                              void* d_out, int out_size)
{
    const float4* scales = (const float4*)d_in[0];  // [N,3]
    const float4* rots   = (const float4*)d_in[1];  // [N,4]
    float4* out          = (float4*)d_out;          // [N,6]

    int n = in_sizes[0] / 3;
    int blocks = (n + TILE - 1) / TILE;
    gs_cov_t512_kernel<<<blocks, TPB>>>(scales, rots, out, n);
}